// round 16
// baseline (speedup 1.0000x reference)
#include <cuda_runtime.h>
#include <math.h>

#define BATCH  2048
#define DIN    2048
#define DB     256
#define NHIST  63488
#define NBANK  (BATCH + NHIST)
#define NC     31
#define CHUNK  64
#define QROWS  32
#define STR    260   /* smem row stride: float4-aligned, 260%32=4 skew */

typedef unsigned long long ull;

__device__ float  g_tf[BATCH * DB];
__device__ float  g_qn[BATCH * DB];
__device__ float  g_norm[NBANK];
__device__ float  g_rcp[NBANK];
__device__ float  g_bns[(size_t)NBANK * DB];   /* class-sorted normalized bank */
__device__ double g_Gp[8 * NC * DB];
__device__ double g_Gd[NC * DB];
__device__ float  g_rex[BATCH * 32];
__device__ int    g_rowlist[NC * BATCH];
__device__ int    g_nrows[NC];
__device__ int    g_pos[NBANK];
__device__ int    g_cofs[NC + 1];
__device__ int    g_bh[256 * NC];
__device__ int    g_base[256 * NC];
__device__ int    g_ltar[BATCH];
__device__ float  g_loss[BATCH];
__device__ int    g_lab64;

__device__ __forceinline__ int get_lab(const int* p, int i) {
    return g_lab64 ? p[2 * i] : p[i];
}
__device__ __forceinline__ int bank_lab(const int* cl, const int* hl, int i) {
    return (i < BATCH) ? get_lab(cl, i) : get_lab(hl, i - BATCH);
}
__device__ __forceinline__ void ffma2(ull& d, ull a, ull b) {
    asm("fma.rn.f32x2 %0, %1, %2, %0;" : "+l"(d) : "l"(a), "l"(b));
}
__device__ __forceinline__ ull dup2(float x) {
    ull r;
    asm("mov.b64 %0, {%1, %1};" : "=l"(r) : "r"(__float_as_uint(x)));
    return r;
}
__device__ __forceinline__ float2 unpack2(ull v) {
    float2 f;
    asm("mov.b64 {%0, %1}, %2;" : "=f"(f.x), "=f"(f.y) : "l"(v));
    return f;
}
/* Markstein: y = RN(1/d) given -> returns RN(x/d) bit-exactly */
__device__ __forceinline__ float div_ms(float x, float d, float y) {
    float q0 = __fmul_rn(x, y);
    float e  = __fmaf_rn(-d, q0, x);
    return __fmaf_rn(e, y, q0);
}

__global__ void k_init(const int* __restrict__ curlab) {
    if (threadIdx.x < NC) g_nrows[threadIdx.x] = 0;
    if (threadIdx.x == 0) {
        int z = 1;
        for (int i = 1; i < 32; i += 2)
            if (curlab[i] != 0) z = 0;
        g_lab64 = z;
    }
}

/* ---- stable counting sort -> g_pos, g_cofs (verified) ---- */
__global__ void k_phist(const int* __restrict__ cl, const int* __restrict__ hl) {
    __shared__ int h[NC];
    const int tid = threadIdx.x;
    if (tid < NC) h[tid] = 0;
    __syncthreads();
    atomicAdd(&h[bank_lab(cl, hl, blockIdx.x * 256 + tid)], 1);
    __syncthreads();
    if (tid < NC) g_bh[blockIdx.x * NC + tid] = h[tid];
}

__global__ void k_pscan() {
    __shared__ int stot[NC];
    const int tid = threadIdx.x;
    if (tid < NC) {
        int t = 0;
        for (int b = 0; b < 256; ++b) t += g_bh[b * NC + tid];
        stot[tid] = t;
    }
    __syncthreads();
    if (tid == 0) {
        int run = 0;
        for (int c = 0; c < NC; ++c) { g_cofs[c] = run; run += stot[c]; }
        g_cofs[NC] = run;
    }
    __syncthreads();
    if (tid < NC) {
        int run = g_cofs[tid];
        for (int b = 0; b < 256; ++b) {
            g_base[b * NC + tid] = run;
            run += g_bh[b * NC + tid];
        }
    }
}

__global__ void k_pplace(const int* __restrict__ cl, const int* __restrict__ hl) {
    __shared__ int lab[256];
    const int tid = threadIdx.x;
    const int b0 = blockIdx.x * 256;
    lab[tid] = bank_lab(cl, hl, b0 + tid);
    __syncthreads();
    if (tid < NC) {
        int run = g_base[blockIdx.x * NC + tid];
        for (int j = 0; j < 256; ++j)
            if (lab[j] == tid) g_pos[b0 + j] = run++;
    }
}

/* ---- tf = relu(target@W1+b1), sequential-k FMA chains (verified) ---- */
#define BM 64
#define BN 64
#define BK 16
__global__ void __launch_bounds__(256) k_gemm1(const float* __restrict__ A,
                                               const float* __restrict__ W,
                                               const float* __restrict__ b1) {
    __shared__ __align__(16) float As[2][BK][BM];
    __shared__ __align__(16) float Bs[2][BK][BN];
    const int tid = threadIdx.x;
    const int m0 = blockIdx.y * BM, n0 = blockIdx.x * BN;
    const int tn = tid & 31, tm = tid >> 5;
    const int ar = tid >> 2, ak = (tid & 3) << 2;
    const int br = tid >> 4, bn4 = (tid & 15) << 2;
    const int NT = DIN / BK;

    float4 aReg = *(const float4*)&A[(size_t)(m0 + ar) * DIN + ak];
    float4 bReg = *(const float4*)&W[(size_t)br * DB + n0 + bn4];
    As[0][ak + 0][ar] = aReg.x; As[0][ak + 1][ar] = aReg.y;
    As[0][ak + 2][ar] = aReg.z; As[0][ak + 3][ar] = aReg.w;
    *(float4*)&Bs[0][br][bn4] = bReg;
    __syncthreads();

    ull acc[4][2] = {};
    for (int kt = 0; kt < NT; ++kt) {
        const int cur = kt & 1;
        if (kt + 1 < NT) {
            const int kg = (kt + 1) * BK;
            aReg = *(const float4*)&A[(size_t)(m0 + ar) * DIN + kg + ak];
            bReg = *(const float4*)&W[(size_t)(kg + br) * DB + n0 + bn4];
        }
        #pragma unroll
        for (int k = 0; k < BK; ++k) {
            double2 av0 = *(const double2*)&As[cur][k][tm * 8];
            double2 av1 = *(const double2*)&As[cur][k][tm * 8 + 4];
            float2  bv  = *(const float2*)&Bs[cur][k][tn * 2];
            ull b0 = dup2(bv.x), b1d = dup2(bv.y);
            ull a0 = __double_as_longlong(av0.x), a1 = __double_as_longlong(av0.y);
            ull a2 = __double_as_longlong(av1.x), a3 = __double_as_longlong(av1.y);
            ffma2(acc[0][0], a0, b0); ffma2(acc[0][1], a0, b1d);
            ffma2(acc[1][0], a1, b0); ffma2(acc[1][1], a1, b1d);
            ffma2(acc[2][0], a2, b0); ffma2(acc[2][1], a2, b1d);
            ffma2(acc[3][0], a3, b0); ffma2(acc[3][1], a3, b1d);
        }
        if (kt + 1 < NT) {
            const int nxt = cur ^ 1;
            As[nxt][ak + 0][ar] = aReg.x; As[nxt][ak + 1][ar] = aReg.y;
            As[nxt][ak + 2][ar] = aReg.z; As[nxt][ak + 3][ar] = aReg.w;
            *(float4*)&Bs[nxt][br][bn4] = bReg;
        }
        __syncthreads();
    }
    const int n = n0 + tn * 2;
    const float bias0 = b1[n], bias1 = b1[n + 1];
    #pragma unroll
    for (int i = 0; i < 4; ++i) {
        float2 c0 = unpack2(acc[i][0]);
        float2 c1 = unpack2(acc[i][1]);
        const int m = m0 + tm * 8 + 2 * i;
        g_tf[(size_t)m * DB + n]           = fmaxf(__fadd_rn(c0.x, bias0), 0.f);
        g_tf[(size_t)m * DB + n + 1]       = fmaxf(__fadd_rn(c1.x, bias1), 0.f);
        g_tf[(size_t)(m + 1) * DB + n]     = fmaxf(__fadd_rn(c0.y, bias0), 0.f);
        g_tf[(size_t)(m + 1) * DB + n + 1] = fmaxf(__fadd_rn(c1.y, bias1), 0.f);
    }
}

/* ---- norms (verified order) + per-row correctly-rounded reciprocal ---- */
__global__ void __launch_bounds__(256) k_norm(const float* __restrict__ hist) {
    __shared__ float tile[8][32][33];
    const int w = threadIdx.x >> 5, lane = threadIdx.x & 31;
    const int row0 = blockIdx.x * 256 + w * 32;
    const float* src = (row0 < BATCH) ? (g_tf + (size_t)row0 * DB)
                                      : (hist + (size_t)(row0 - BATCH) * DB);
    float acc = 0.f;
    for (int ch = 0; ch < 8; ++ch) {
        #pragma unroll 8
        for (int r = 0; r < 32; ++r)
            tile[w][r][lane] = src[(size_t)r * DB + ch * 32 + lane];
        __syncwarp();
        #pragma unroll 8
        for (int j = 0; j < 32; ++j) {
            float v = tile[w][lane][j];
            acc = __fadd_rn(acc, __fmul_rn(v, v));
        }
        __syncwarp();
    }
    const float nm = __fsqrt_rn(acc);
    g_norm[row0 + lane] = nm;
    g_rcp[row0 + lane] = __fdiv_rn(1.0f, __fadd_rn(nm, 1e-12f));
}

/* ---- normalize via Markstein (bit-identical to __fdiv_rn) + scatter ---- */
__global__ void __launch_bounds__(256) k_qnrm(const float* __restrict__ hist) {
    const int gid = blockIdx.x * 256 + threadIdx.x;
    const int r = gid >> 6, q = (gid & 63) << 2;
    const float* src = (r < BATCH) ? (g_tf + (size_t)r * DB)
                                   : (hist + (size_t)(r - BATCH) * DB);
    float4 v = *(const float4*)(src + q);
    const float den = __fadd_rn(g_norm[r], 1e-12f);
    const float y = g_rcp[r];
    float4 o;
    o.x = div_ms(v.x, den, y); o.y = div_ms(v.y, den, y);
    o.z = div_ms(v.z, den, y); o.w = div_ms(v.w, den, y);
    *(float4*)(g_bns + (size_t)g_pos[r] * DB + q) = o;
    if (r < BATCH) *(float4*)(g_qn + (size_t)r * DB + q) = o;
}

/* ---- double class sums over sorted segments ---- */
__global__ void k_gsum() {   /* grid (NC, 8), block 256 */
    const int c = blockIdx.x, p = blockIdx.y, d = threadIdx.x;
    const int lo = g_cofs[c], cnt = g_cofs[c + 1] - lo;
    const int i0 = lo + (int)(((long long)cnt * p) >> 3);
    const int i1 = lo + (int)(((long long)cnt * (p + 1)) >> 3);
    double a0 = 0, a1 = 0, a2 = 0, a3 = 0;
    int i = i0;
    for (; i + 4 <= i1; i += 4) {
        a0 += (double)g_bns[(size_t)i * DB + d];
        a1 += (double)g_bns[(size_t)(i + 1) * DB + d];
        a2 += (double)g_bns[(size_t)(i + 2) * DB + d];
        a3 += (double)g_bns[(size_t)(i + 3) * DB + d];
    }
    for (; i < i1; ++i) a0 += (double)g_bns[(size_t)i * DB + d];
    g_Gp[(p * NC + c) * DB + d] = (a0 + a1) + (a2 + a3);
}

__global__ void k_gred() {   /* grid NC, block 256 */
    const int c = blockIdx.x, d = threadIdx.x;
    double s = 0;
    for (int p = 0; p < 8; ++p) s += g_Gp[(p * NC + c) * DB + d];
    g_Gd[c * DB + d] = s;
}

/* ---- screen: double means + worst-case margins -> contenders ---- */
__global__ void __launch_bounds__(256) k_screen() {  /* grid 256 */
    __shared__ float qs[8][256];
    const int w = threadIdx.x >> 5, lane = threadIdx.x & 31;
    const int b = blockIdx.x * 8 + w;
    for (int j = lane; j < 256; j += 32) qs[w][j] = g_qn[(size_t)b * DB + j];
    __syncwarp();
    double t = 1e300, Mc = 0.0;
    if (lane < NC) {
        const int lo = g_cofs[lane], cnt = g_cofs[lane + 1] - lo;
        if (cnt > 0) {
            const double* G = &g_Gd[lane * DB];
            double a0 = 0, a1 = 0, a2 = 0, a3 = 0;
            #pragma unroll 4
            for (int d = 0; d < 256; d += 4) {
                a0 += (double)qs[w][d]     * G[d];
                a1 += (double)qs[w][d + 1] * G[d + 1];
                a2 += (double)qs[w][d + 2] * G[d + 2];
                a3 += (double)qs[w][d + 3] * G[d + 3];
            }
            double dot = (a0 + a1) + (a2 + a3);
            t = ((double)cnt - dot) / (double)cnt;
            Mc = 6.05e-8 * (double)(cnt + 8) + 2.5e-5;
        }
    }
    double tmin = t, Mmin = Mc;
    #pragma unroll
    for (int off = 16; off; off >>= 1) {
        double ov = __shfl_xor_sync(0xffffffffu, tmin, off);
        double om = __shfl_xor_sync(0xffffffffu, Mmin, off);
        if (ov < tmin) { tmin = ov; Mmin = om; }
    }
    const bool cont = (lane < NC) && (t <= tmin + Mc + Mmin);
    const unsigned mask = __ballot_sync(0xffffffffu, cont);
    g_rex[b * 32 + lane] = __int_as_float(0x7f800000);
    if (__popc(mask) == 1) {
        if (lane == 0) g_ltar[b] = __ffs(mask) - 1;
    } else {
        if (lane == 0) g_ltar[b] = -1;
        if (cont) {
            int k = atomicAdd(&g_nrows[lane], 1);
            g_rowlist[lane * BATCH + k] = b;
        }
    }
}

/* ---- exact pass v2: 32 q-rows/block, double-buffered chunks ----
   Bit-exact: per (b,c) ascending-d __fmaf_rn dot chains, fl(1-dot),
   ascending-segment-order sequential __fadd_rn fold, __fdiv_rn mean.
   float4 decode: row = u>>6 (64 float4 per 256-float row), d4 = (u&63)*4. */
extern __shared__ float dynsm[];
__global__ void __launch_bounds__(256) k_exact() {  /* grid (NC, 64) */
    const int c = blockIdx.x;
    const int nr = g_nrows[c];
    const int q0i = blockIdx.y * QROWS;
    if (q0i >= nr) return;
    float* As = dynsm;                       /* [2][64][STR] */
    float* qs = dynsm + 2 * CHUNK * STR;     /* [32][STR]    */
    float* fb = qs + QROWS * STR;            /* [8][4][64]   */
    const int tid = threadIdx.x;
    const int w = tid >> 5, lane = tid & 31;
    const int lo = g_cofs[c], cnt = g_cofs[c + 1] - lo;

    /* load up to 32 contender q rows */
    for (int u = tid; u < QROWS * 256; u += 256) {
        const int s = u >> 8, d = u & 255;
        const int qi = q0i + s;
        const int b = (qi < nr) ? g_rowlist[c * BATCH + qi] : 0;
        qs[s * STR + d] = g_qn[(size_t)b * DB + d];
    }

    const int nch = (cnt + CHUNK - 1) / CHUNK;
    float4 ld[16];
    /* prologue: chunk 0 into regs then buffer 0 */
    {
        #pragma unroll
        for (int i = 0; i < 16; ++i) {
            const int u = tid + 256 * i;
            const int r = u >> 6, d4 = (u & 63) << 2;
            ld[i] = (r < cnt) ? *(const float4*)&g_bns[(size_t)(lo + r) * DB + d4]
                              : make_float4(0.f, 0.f, 0.f, 0.f);
        }
        #pragma unroll
        for (int i = 0; i < 16; ++i) {
            const int u = tid + 256 * i;
            const int r = u >> 6, d4 = (u & 63) << 2;
            *(float4*)&As[r * STR + d4] = ld[i];
        }
    }
    __syncthreads();

    const int myq = q0i + w * 4 + lane;         /* lane<4: fold row validity */
    const bool foldv = (lane < 4) && (myq < nr);
    float s = 0.f;

    for (int ch = 0; ch < nch; ++ch) {
        const int cur = ch & 1;
        if (ch + 1 < nch) {
            const int base = (ch + 1) * CHUNK;
            #pragma unroll
            for (int i = 0; i < 16; ++i) {
                const int u = tid + 256 * i;
                const int r = base + (u >> 6), d4 = (u & 63) << 2;
                ld[i] = (r < cnt) ? *(const float4*)&g_bns[(size_t)(lo + r) * DB + d4]
                                  : make_float4(0.f, 0.f, 0.f, 0.f);
            }
        }
        int m = cnt - ch * CHUNK;
        if (m > CHUNK) m = CHUNK;
        const float* bufc = As + cur * (CHUNK * STR);
        const bool v0 = lane < m, v1 = lane + 32 < m;
        #pragma unroll
        for (int qi = 0; qi < 4; ++qi) {
            if (q0i + w * 4 + qi < nr) {
                const float* qp = &qs[(w * 4 + qi) * STR];
                const float* r0 = bufc + lane * STR;
                const float* r1 = bufc + (lane + 32) * STR;
                float a0 = 0.f, a1 = 0.f;
                #pragma unroll 8
                for (int d = 0; d < 256; ++d) {
                    a0 = __fmaf_rn(qp[d], r0[d], a0);
                    a1 = __fmaf_rn(qp[d], r1[d], a1);
                }
                if (v0) fb[(w * 4 + qi) * 64 + lane]      = __fadd_rn(1.0f, -a0);
                if (v1) fb[(w * 4 + qi) * 64 + lane + 32] = __fadd_rn(1.0f, -a1);
            }
        }
        __syncwarp();
        if (foldv) {
            const float* f = &fb[(w * 4 + lane) * 64];
            for (int j = 0; j < m; ++j) s = __fadd_rn(s, f[j]);
        }
        __syncwarp();
        if (ch + 1 < nch) {
            float* bufn = As + (cur ^ 1) * (CHUNK * STR);
            #pragma unroll
            for (int i = 0; i < 16; ++i) {
                const int u = tid + 256 * i;
                const int r = u >> 6, d4 = (u & 63) << 2;
                *(float4*)&bufn[r * STR + d4] = ld[i];
            }
        }
        __syncthreads();
    }
    if (foldv) {
        const int b = g_rowlist[c * BATCH + myq];
        g_rex[b * 32 + c] = __fdiv_rn(s, (float)cnt);
    }
}

/* ---- decide: single-contender fast path or exact argmin ---- */
__global__ void __launch_bounds__(256) k_decide(float* __restrict__ out) {
    const int w = threadIdx.x >> 5, lane = threadIdx.x & 31;
    const int b = blockIdx.x * 8 + w;
    int lt = g_ltar[b];
    if (lt < 0) {
        float v = (lane < NC) ? g_rex[b * 32 + lane] : __int_as_float(0x7f800000);
        int idx = lane;
        #pragma unroll
        for (int off = 16; off; off >>= 1) {
            float ov = __shfl_xor_sync(0xffffffffu, v, off);
            int oi = __shfl_xor_sync(0xffffffffu, idx, off);
            if (ov < v || (ov == v && oi < idx)) { v = ov; idx = oi; }
        }
        lt = idx;
        if (lane == 0) g_ltar[b] = lt;
    }
    if (lane == 0) out[BATCH + b] = (float)lt;
}

/* ---- logits, argmax, per-row loss (verified) ---- */
__global__ void __launch_bounds__(256) k_logits(const float* __restrict__ Wc,
                                                const float* __restrict__ bc,
                                                float* __restrict__ out) {
    __shared__ float Ws[DB * 32];
    __shared__ float bcs[32];
    __shared__ float qrow[8][DB];
    const int tid = threadIdx.x;
    for (int i = tid; i < DB * 32; i += 256) {
        int d = i >> 5, c = i & 31;
        Ws[i] = (c < NC) ? Wc[d * NC + c] : 0.f;
    }
    if (tid < 32) bcs[tid] = (tid < NC) ? bc[tid] : 0.f;
    __syncthreads();
    const int w = tid >> 5, lane = tid & 31;
    const int b = blockIdx.x * 8 + w;
    *(float4*)&qrow[w][lane * 8]     = *(const float4*)(g_tf + (size_t)b * DB + lane * 8);
    *(float4*)&qrow[w][lane * 8 + 4] = *(const float4*)(g_tf + (size_t)b * DB + lane * 8 + 4);
    __syncwarp();
    float acc = 0.f;
    #pragma unroll 8
    for (int d = 0; d < DB; ++d) acc = __fmaf_rn(qrow[w][d], Ws[d * 32 + lane], acc);
    float logit = (lane < NC) ? __fadd_rn(acc, bcs[lane]) : -__int_as_float(0x7f800000);
    float v = logit;
    int idx = lane;
    #pragma unroll
    for (int off = 16; off; off >>= 1) {
        float ov = __shfl_xor_sync(0xffffffffu, v, off);
        int oi = __shfl_xor_sync(0xffffffffu, idx, off);
        if (ov > v || (ov == v && oi < idx)) { v = ov; idx = oi; }
    }
    const float m = v;
    float e = (lane < NC) ? expf(logit - m) : 0.f;
    #pragma unroll
    for (int off = 16; off; off >>= 1) e += __shfl_xor_sync(0xffffffffu, e, off);
    const int ltar = g_ltar[b];
    const float lt = __shfl_sync(0xffffffffu, logit, ltar);
    if (lane == 0) {
        out[b] = (float)idx;
        g_loss[b] = (logf(e) + m) - lt;
    }
}

__global__ void __launch_bounds__(256) k_final(float* __restrict__ out) {
    __shared__ float red[256];
    const int tid = threadIdx.x;
    float s = 0.f;
    for (int i = tid; i < BATCH; i += 256) s += g_loss[i];
    red[tid] = s;
    __syncthreads();
    for (int st = 128; st; st >>= 1) {
        if (tid < st) red[tid] += red[tid + st];
        __syncthreads();
    }
    if (tid == 0) out[2 * BATCH] = red[0] / (float)BATCH;
}

extern "C" void kernel_launch(void* const* d_in, const int* in_sizes, int n_in,
                              void* d_out, int out_size) {
    const float* target  = (const float*)d_in[0];
    const int*   curlab  = (const int*)d_in[1];
    const float* hist    = (const float*)d_in[2];
    const int*   histlab = (const int*)d_in[3];
    const float* W1      = (const float*)d_in[4];
    const float* b1      = (const float*)d_in[5];
    const float* Wc      = (const float*)d_in[6];
    const float* bc      = (const float*)d_in[7];
    float* out = (float*)d_out;

    const int exsmem = (2 * CHUNK * STR + QROWS * STR + 8 * 4 * 64) * 4;
    cudaFuncSetAttribute(k_exact, cudaFuncAttributeMaxDynamicSharedMemorySize, exsmem);

    k_init<<<1, 32>>>(curlab);
    k_phist<<<NBANK / 256, 256>>>(curlab, histlab);
    k_pscan<<<1, 32>>>();
    k_pplace<<<NBANK / 256, 256>>>(curlab, histlab);
    dim3 g1(DB / BN, BATCH / BM);
    k_gemm1<<<g1, 256>>>(target, W1, b1);
    k_norm<<<NBANK / 256, 256>>>(hist);
    k_qnrm<<<(NBANK * 64) / 256, 256>>>(hist);
    dim3 gs(NC, 8);
    k_gsum<<<gs, 256>>>();
    k_gred<<<NC, 256>>>();
    k_screen<<<BATCH / 8, 256>>>();
    dim3 ge(NC, 64);
    k_exact<<<ge, 256, exsmem>>>();
    k_decide<<<BATCH / 8, 256>>>(out);
    k_logits<<<BATCH / 8, 256>>>(Wc, bc, out);
    k_final<<<1, 256>>>(out);
}

// round 17
// speedup vs baseline: 1.3500x; 1.3500x over previous
#include <cuda_runtime.h>
#include <math.h>

#define BATCH  2048
#define DIN    2048
#define DB     256
#define NHIST  63488
#define NBANK  (BATCH + NHIST)
#define NC     31
#define CHUNK  64
#define QROWS  32
#define STR    260

typedef unsigned long long ull;

__device__ float  g_tf[BATCH * DB];
__device__ float  g_qn[BATCH * DB];
__device__ float  g_norm[NBANK];
__device__ float  g_rcp[NBANK];
__device__ float  g_bns[(size_t)NBANK * DB];
__device__ double g_Gp[8 * NC * DB];
__device__ double g_Gd[NC * DB];
__device__ float  g_rex[BATCH * 32];
__device__ int    g_rowlist[NC * BATCH];
__device__ int    g_nrows[NC];
__device__ int    g_pos[NBANK];
__device__ int    g_cofs[NC + 1];
__device__ int    g_bh[256 * NC];
__device__ int    g_base[256 * NC];
__device__ int    g_ltar[BATCH];
__device__ float  g_loss[BATCH];
__device__ int    g_lab64;

__device__ __forceinline__ int get_lab(const int* p, int i) {
    return g_lab64 ? p[2 * i] : p[i];
}
__device__ __forceinline__ int bank_lab(const int* cl, const int* hl, int i) {
    return (i < BATCH) ? get_lab(cl, i) : get_lab(hl, i - BATCH);
}
__device__ __forceinline__ void ffma2(ull& d, ull a, ull b) {
    asm("fma.rn.f32x2 %0, %1, %2, %0;" : "+l"(d) : "l"(a), "l"(b));
}
__device__ __forceinline__ ull dup2(float x) {
    ull r;
    asm("mov.b64 %0, {%1, %1};" : "=l"(r) : "r"(__float_as_uint(x)));
    return r;
}
__device__ __forceinline__ float2 unpack2(ull v) {
    float2 f;
    asm("mov.b64 {%0, %1}, %2;" : "=f"(f.x), "=f"(f.y) : "l"(v));
    return f;
}
__device__ __forceinline__ float div_ms(float x, float d, float y) {
    float q0 = __fmul_rn(x, y);
    float e  = __fmaf_rn(-d, q0, x);
    return __fmaf_rn(e, y, q0);
}

__global__ void k_init(const int* __restrict__ curlab) {
    if (threadIdx.x < NC) g_nrows[threadIdx.x] = 0;
    if (threadIdx.x == 0) {
        int z = 1;
        for (int i = 1; i < 32; i += 2)
            if (curlab[i] != 0) z = 0;
        g_lab64 = z;
    }
}

__global__ void k_phist(const int* __restrict__ cl, const int* __restrict__ hl) {
    __shared__ int h[NC];
    const int tid = threadIdx.x;
    if (tid < NC) h[tid] = 0;
    __syncthreads();
    atomicAdd(&h[bank_lab(cl, hl, blockIdx.x * 256 + tid)], 1);
    __syncthreads();
    if (tid < NC) g_bh[blockIdx.x * NC + tid] = h[tid];
}

__global__ void k_pscan() {
    __shared__ int stot[NC];
    const int tid = threadIdx.x;
    if (tid < NC) {
        int t = 0;
        for (int b = 0; b < 256; ++b) t += g_bh[b * NC + tid];
        stot[tid] = t;
    }
    __syncthreads();
    if (tid == 0) {
        int run = 0;
        for (int c = 0; c < NC; ++c) { g_cofs[c] = run; run += stot[c]; }
        g_cofs[NC] = run;
    }
    __syncthreads();
    if (tid < NC) {
        int run = g_cofs[tid];
        for (int b = 0; b < 256; ++b) {
            g_base[b * NC + tid] = run;
            run += g_bh[b * NC + tid];
        }
    }
}

__global__ void k_pplace(const int* __restrict__ cl, const int* __restrict__ hl) {
    __shared__ int lab[256];
    const int tid = threadIdx.x;
    const int b0 = blockIdx.x * 256;
    lab[tid] = bank_lab(cl, hl, b0 + tid);
    __syncthreads();
    if (tid < NC) {
        int run = g_base[blockIdx.x * NC + tid];
        for (int j = 0; j < 256; ++j)
            if (lab[j] == tid) g_pos[b0 + j] = run++;
    }
}

#define BM 64
#define BN 64
#define BK 16
__global__ void __launch_bounds__(256) k_gemm1(const float* __restrict__ A,
                                               const float* __restrict__ W,
                                               const float* __restrict__ b1) {
    __shared__ __align__(16) float As[2][BK][BM];
    __shared__ __align__(16) float Bs[2][BK][BN];
    const int tid = threadIdx.x;
    const int m0 = blockIdx.y * BM, n0 = blockIdx.x * BN;
    const int tn = tid & 31, tm = tid >> 5;
    const int ar = tid >> 2, ak = (tid & 3) << 2;
    const int br = tid >> 4, bn4 = (tid & 15) << 2;
    const int NT = DIN / BK;

    float4 aReg = *(const float4*)&A[(size_t)(m0 + ar) * DIN + ak];
    float4 bReg = *(const float4*)&W[(size_t)br * DB + n0 + bn4];
    As[0][ak + 0][ar] = aReg.x; As[0][ak + 1][ar] = aReg.y;
    As[0][ak + 2][ar] = aReg.z; As[0][ak + 3][ar] = aReg.w;
    *(float4*)&Bs[0][br][bn4] = bReg;
    __syncthreads();

    ull acc[4][2] = {};
    for (int kt = 0; kt < NT; ++kt) {
        const int cur = kt & 1;
        if (kt + 1 < NT) {
            const int kg = (kt + 1) * BK;
            aReg = *(const float4*)&A[(size_t)(m0 + ar) * DIN + kg + ak];
            bReg = *(const float4*)&W[(size_t)(kg + br) * DB + n0 + bn4];
        }
        #pragma unroll
        for (int k = 0; k < BK; ++k) {
            double2 av0 = *(const double2*)&As[cur][k][tm * 8];
            double2 av1 = *(const double2*)&As[cur][k][tm * 8 + 4];
            float2  bv  = *(const float2*)&Bs[cur][k][tn * 2];
            ull b0 = dup2(bv.x), b1d = dup2(bv.y);
            ull a0 = __double_as_longlong(av0.x), a1 = __double_as_longlong(av0.y);
            ull a2 = __double_as_longlong(av1.x), a3 = __double_as_longlong(av1.y);
            ffma2(acc[0][0], a0, b0); ffma2(acc[0][1], a0, b1d);
            ffma2(acc[1][0], a1, b0); ffma2(acc[1][1], a1, b1d);
            ffma2(acc[2][0], a2, b0); ffma2(acc[2][1], a2, b1d);
            ffma2(acc[3][0], a3, b0); ffma2(acc[3][1], a3, b1d);
        }
        if (kt + 1 < NT) {
            const int nxt = cur ^ 1;
            As[nxt][ak + 0][ar] = aReg.x; As[nxt][ak + 1][ar] = aReg.y;
            As[nxt][ak + 2][ar] = aReg.z; As[nxt][ak + 3][ar] = aReg.w;
            *(float4*)&Bs[nxt][br][bn4] = bReg;
        }
        __syncthreads();
    }
    const int n = n0 + tn * 2;
    const float bias0 = b1[n], bias1 = b1[n + 1];
    #pragma unroll
    for (int i = 0; i < 4; ++i) {
        float2 c0 = unpack2(acc[i][0]);
        float2 c1 = unpack2(acc[i][1]);
        const int m = m0 + tm * 8 + 2 * i;
        g_tf[(size_t)m * DB + n]           = fmaxf(__fadd_rn(c0.x, bias0), 0.f);
        g_tf[(size_t)m * DB + n + 1]       = fmaxf(__fadd_rn(c1.x, bias1), 0.f);
        g_tf[(size_t)(m + 1) * DB + n]     = fmaxf(__fadd_rn(c0.y, bias0), 0.f);
        g_tf[(size_t)(m + 1) * DB + n + 1] = fmaxf(__fadd_rn(c1.y, bias1), 0.f);
    }
}

__global__ void __launch_bounds__(256) k_norm(const float* __restrict__ hist) {
    __shared__ float tile[8][32][33];
    const int w = threadIdx.x >> 5, lane = threadIdx.x & 31;
    const int row0 = blockIdx.x * 256 + w * 32;
    const float* src = (row0 < BATCH) ? (g_tf + (size_t)row0 * DB)
                                      : (hist + (size_t)(row0 - BATCH) * DB);
    float acc = 0.f;
    for (int ch = 0; ch < 8; ++ch) {
        #pragma unroll 8
        for (int r = 0; r < 32; ++r)
            tile[w][r][lane] = src[(size_t)r * DB + ch * 32 + lane];
        __syncwarp();
        #pragma unroll 8
        for (int j = 0; j < 32; ++j) {
            float v = tile[w][lane][j];
            acc = __fadd_rn(acc, __fmul_rn(v, v));
        }
        __syncwarp();
    }
    const float nm = __fsqrt_rn(acc);
    g_norm[row0 + lane] = nm;
    g_rcp[row0 + lane] = __fdiv_rn(1.0f, __fadd_rn(nm, 1e-12f));
}

__global__ void __launch_bounds__(256) k_qnrm(const float* __restrict__ hist) {
    const int gid = blockIdx.x * 256 + threadIdx.x;
    const int r = gid >> 6, q = (gid & 63) << 2;
    const float* src = (r < BATCH) ? (g_tf + (size_t)r * DB)
                                   : (hist + (size_t)(r - BATCH) * DB);
    float4 v = *(const float4*)(src + q);
    const float den = __fadd_rn(g_norm[r], 1e-12f);
    const float y = g_rcp[r];
    float4 o;
    o.x = div_ms(v.x, den, y); o.y = div_ms(v.y, den, y);
    o.z = div_ms(v.z, den, y); o.w = div_ms(v.w, den, y);
    *(float4*)(g_bns + (size_t)g_pos[r] * DB + q) = o;
    if (r < BATCH) *(float4*)(g_qn + (size_t)r * DB + q) = o;
}

__global__ void k_gsum() {
    const int c = blockIdx.x, p = blockIdx.y, d = threadIdx.x;
    const int lo = g_cofs[c], cnt = g_cofs[c + 1] - lo;
    const int i0 = lo + (int)(((long long)cnt * p) >> 3);
    const int i1 = lo + (int)(((long long)cnt * (p + 1)) >> 3);
    double a0 = 0, a1 = 0, a2 = 0, a3 = 0;
    int i = i0;
    for (; i + 4 <= i1; i += 4) {
        a0 += (double)g_bns[(size_t)i * DB + d];
        a1 += (double)g_bns[(size_t)(i + 1) * DB + d];
        a2 += (double)g_bns[(size_t)(i + 2) * DB + d];
        a3 += (double)g_bns[(size_t)(i + 3) * DB + d];
    }
    for (; i < i1; ++i) a0 += (double)g_bns[(size_t)i * DB + d];
    g_Gp[(p * NC + c) * DB + d] = (a0 + a1) + (a2 + a3);
}

__global__ void k_gred() {
    const int c = blockIdx.x, d = threadIdx.x;
    double s = 0;
    for (int p = 0; p < 8; ++p) s += g_Gp[(p * NC + c) * DB + d];
    g_Gd[c * DB + d] = s;
}

__global__ void __launch_bounds__(256) k_screen() {
    __shared__ float qs[8][256];
    const int w = threadIdx.x >> 5, lane = threadIdx.x & 31;
    const int b = blockIdx.x * 8 + w;
    for (int j = lane; j < 256; j += 32) qs[w][j] = g_qn[(size_t)b * DB + j];
    __syncwarp();
    double t = 1e300, Mc = 0.0;
    if (lane < NC) {
        const int lo = g_cofs[lane], cnt = g_cofs[lane + 1] - lo;
        if (cnt > 0) {
            const double* G = &g_Gd[lane * DB];
            double a0 = 0, a1 = 0, a2 = 0, a3 = 0;
            #pragma unroll 4
            for (int d = 0; d < 256; d += 4) {
                a0 += (double)qs[w][d]     * G[d];
                a1 += (double)qs[w][d + 1] * G[d + 1];
                a2 += (double)qs[w][d + 2] * G[d + 2];
                a3 += (double)qs[w][d + 3] * G[d + 3];
            }
            double dot = (a0 + a1) + (a2 + a3);
            t = ((double)cnt - dot) / (double)cnt;
            Mc = 6.05e-8 * (double)(cnt + 8) + 2.5e-5;
        }
    }
    double tmin = t, Mmin = Mc;
    #pragma unroll
    for (int off = 16; off; off >>= 1) {
        double ov = __shfl_xor_sync(0xffffffffu, tmin, off);
        double om = __shfl_xor_sync(0xffffffffu, Mmin, off);
        if (ov < tmin) { tmin = ov; Mmin = om; }
    }
    const bool cont = (lane < NC) && (t <= tmin + Mc + Mmin);
    const unsigned mask = __ballot_sync(0xffffffffu, cont);
    g_rex[b * 32 + lane] = __int_as_float(0x7f800000);
    if (__popc(mask) == 1) {
        if (lane == 0) g_ltar[b] = __ffs(mask) - 1;
    } else {
        if (lane == 0) g_ltar[b] = -1;
        if (cont) {
            int k = atomicAdd(&g_nrows[lane], 1);
            g_rowlist[lane * BATCH + k] = b;
        }
    }
}

/* ---- exact pass v3: d-outermost, bank rows loaded once per 4 q-rows ---- */
extern __shared__ float dynsm[];
__global__ void __launch_bounds__(256) k_exact() {  /* grid (NC, 64) */
    const int c = blockIdx.x;
    const int nr = g_nrows[c];
    const int q0i = blockIdx.y * QROWS;
    if (q0i >= nr) return;
    float* As = dynsm;                       /* [2][64][STR] */
    float* qs = dynsm + 2 * CHUNK * STR;     /* [32][STR]    */
    float* fb = qs + QROWS * STR;            /* [8][4][64]   */
    const int tid = threadIdx.x;
    const int w = tid >> 5, lane = tid & 31;
    const int lo = g_cofs[c], cnt = g_cofs[c + 1] - lo;

    for (int u = tid; u < QROWS * 256; u += 256) {
        const int s = u >> 8, d = u & 255;
        const int qi = q0i + s;
        const int b = (qi < nr) ? g_rowlist[c * BATCH + qi] : 0;
        qs[s * STR + d] = g_qn[(size_t)b * DB + d];
    }

    const int nch = (cnt + CHUNK - 1) / CHUNK;
    float4 ld[16];
    {
        #pragma unroll
        for (int i = 0; i < 16; ++i) {
            const int u = tid + 256 * i;
            const int r = u >> 6, d4 = (u & 63) << 2;
            ld[i] = (r < cnt) ? *(const float4*)&g_bns[(size_t)(lo + r) * DB + d4]
                              : make_float4(0.f, 0.f, 0.f, 0.f);
        }
        #pragma unroll
        for (int i = 0; i < 16; ++i) {
            const int u = tid + 256 * i;
            const int r = u >> 6, d4 = (u & 63) << 2;
            *(float4*)&As[r * STR + d4] = ld[i];
        }
    }
    __syncthreads();

    const int myq = q0i + w * 4 + lane;
    const bool foldv = (lane < 4) && (myq < nr);
    float s = 0.f;

    for (int ch = 0; ch < nch; ++ch) {
        const int cur = ch & 1;
        if (ch + 1 < nch) {
            const int base = (ch + 1) * CHUNK;
            #pragma unroll
            for (int i = 0; i < 16; ++i) {
                const int u = tid + 256 * i;
                const int r = base + (u >> 6), d4 = (u & 63) << 2;
                ld[i] = (r < cnt) ? *(const float4*)&g_bns[(size_t)(lo + r) * DB + d4]
                                  : make_float4(0.f, 0.f, 0.f, 0.f);
            }
        }
        int m = cnt - ch * CHUNK;
        if (m > CHUNK) m = CHUNK;
        const float* bufc = As + cur * (CHUNK * STR);
        const float* r0 = bufc + lane * STR;
        const float* r1 = bufc + (lane + 32) * STR;
        const float* q0 = &qs[(w * 4 + 0) * STR];
        const float* q1 = &qs[(w * 4 + 1) * STR];
        const float* q2 = &qs[(w * 4 + 2) * STR];
        const float* q3 = &qs[(w * 4 + 3) * STR];
        float a0q0 = 0.f, a0q1 = 0.f, a0q2 = 0.f, a0q3 = 0.f;
        float a1q0 = 0.f, a1q1 = 0.f, a1q2 = 0.f, a1q3 = 0.f;
        #pragma unroll 4
        for (int d = 0; d < 256; d += 4) {
            float4 x0 = *(const float4*)(r0 + d);
            float4 x1 = *(const float4*)(r1 + d);
            float4 v0 = *(const float4*)(q0 + d);
            float4 v1 = *(const float4*)(q1 + d);
            float4 v2 = *(const float4*)(q2 + d);
            float4 v3 = *(const float4*)(q3 + d);
            a0q0 = __fmaf_rn(v0.x, x0.x, a0q0); a0q0 = __fmaf_rn(v0.y, x0.y, a0q0);
            a0q0 = __fmaf_rn(v0.z, x0.z, a0q0); a0q0 = __fmaf_rn(v0.w, x0.w, a0q0);
            a0q1 = __fmaf_rn(v1.x, x0.x, a0q1); a0q1 = __fmaf_rn(v1.y, x0.y, a0q1);
            a0q1 = __fmaf_rn(v1.z, x0.z, a0q1); a0q1 = __fmaf_rn(v1.w, x0.w, a0q1);
            a0q2 = __fmaf_rn(v2.x, x0.x, a0q2); a0q2 = __fmaf_rn(v2.y, x0.y, a0q2);
            a0q2 = __fmaf_rn(v2.z, x0.z, a0q2); a0q2 = __fmaf_rn(v2.w, x0.w, a0q2);
            a0q3 = __fmaf_rn(v3.x, x0.x, a0q3); a0q3 = __fmaf_rn(v3.y, x0.y, a0q3);
            a0q3 = __fmaf_rn(v3.z, x0.z, a0q3); a0q3 = __fmaf_rn(v3.w, x0.w, a0q3);
            a1q0 = __fmaf_rn(v0.x, x1.x, a1q0); a1q0 = __fmaf_rn(v0.y, x1.y, a1q0);
            a1q0 = __fmaf_rn(v0.z, x1.z, a1q0); a1q0 = __fmaf_rn(v0.w, x1.w, a1q0);
            a1q1 = __fmaf_rn(v1.x, x1.x, a1q1); a1q1 = __fmaf_rn(v1.y, x1.y, a1q1);
            a1q1 = __fmaf_rn(v1.z, x1.z, a1q1); a1q1 = __fmaf_rn(v1.w, x1.w, a1q1);
            a1q2 = __fmaf_rn(v2.x, x1.x, a1q2); a1q2 = __fmaf_rn(v2.y, x1.y, a1q2);
            a1q2 = __fmaf_rn(v2.z, x1.z, a1q2); a1q2 = __fmaf_rn(v2.w, x1.w, a1q2);
            a1q3 = __fmaf_rn(v3.x, x1.x, a1q3); a1q3 = __fmaf_rn(v3.y, x1.y, a1q3);
            a1q3 = __fmaf_rn(v3.z, x1.z, a1q3); a1q3 = __fmaf_rn(v3.w, x1.w, a1q3);
        }
        const bool v0ok = lane < m, v1ok = lane + 32 < m;
        const float a0arr[4] = {a0q0, a0q1, a0q2, a0q3};
        const float a1arr[4] = {a1q0, a1q1, a1q2, a1q3};
        #pragma unroll
        for (int qi = 0; qi < 4; ++qi) {
            if (q0i + w * 4 + qi < nr) {
                if (v0ok) fb[(w * 4 + qi) * 64 + lane]      = __fadd_rn(1.0f, -a0arr[qi]);
                if (v1ok) fb[(w * 4 + qi) * 64 + lane + 32] = __fadd_rn(1.0f, -a1arr[qi]);
            }
        }
        __syncwarp();
        if (foldv) {
            const float* f = &fb[(w * 4 + lane) * 64];
            for (int j = 0; j < m; ++j) s = __fadd_rn(s, f[j]);
        }
        __syncwarp();
        if (ch + 1 < nch) {
            float* bufn = As + (cur ^ 1) * (CHUNK * STR);
            #pragma unroll
            for (int i = 0; i < 16; ++i) {
                const int u = tid + 256 * i;
                const int r = u >> 6, d4 = (u & 63) << 2;
                *(float4*)&bufn[r * STR + d4] = ld[i];
            }
        }
        __syncthreads();
    }
    if (foldv) {
        const int b = g_rowlist[c * BATCH + myq];
        g_rex[b * 32 + c] = __fdiv_rn(s, (float)cnt);
    }
}

__global__ void __launch_bounds__(256) k_decide(float* __restrict__ out) {
    const int w = threadIdx.x >> 5, lane = threadIdx.x & 31;
    const int b = blockIdx.x * 8 + w;
    int lt = g_ltar[b];
    if (lt < 0) {
        float v = (lane < NC) ? g_rex[b * 32 + lane] : __int_as_float(0x7f800000);
        int idx = lane;
        #pragma unroll
        for (int off = 16; off; off >>= 1) {
            float ov = __shfl_xor_sync(0xffffffffu, v, off);
            int oi = __shfl_xor_sync(0xffffffffu, idx, off);
            if (ov < v || (ov == v && oi < idx)) { v = ov; idx = oi; }
        }
        lt = idx;
        if (lane == 0) g_ltar[b] = lt;
    }
    if (lane == 0) out[BATCH + b] = (float)lt;
}

__global__ void __launch_bounds__(256) k_logits(const float* __restrict__ Wc,
                                                const float* __restrict__ bc,
                                                float* __restrict__ out) {
    __shared__ float Ws[DB * 32];
    __shared__ float bcs[32];
    __shared__ float qrow[8][DB];
    const int tid = threadIdx.x;
    for (int i = tid; i < DB * 32; i += 256) {
        int d = i >> 5, c = i & 31;
        Ws[i] = (c < NC) ? Wc[d * NC + c] : 0.f;
    }
    if (tid < 32) bcs[tid] = (tid < NC) ? bc[tid] : 0.f;
    __syncthreads();
    const int w = tid >> 5, lane = tid & 31;
    const int b = blockIdx.x * 8 + w;
    *(float4*)&qrow[w][lane * 8]     = *(const float4*)(g_tf + (size_t)b * DB + lane * 8);
    *(float4*)&qrow[w][lane * 8 + 4] = *(const float4*)(g_tf + (size_t)b * DB + lane * 8 + 4);
    __syncwarp();
    float acc = 0.f;
    #pragma unroll 8
    for (int d = 0; d < DB; ++d) acc = __fmaf_rn(qrow[w][d], Ws[d * 32 + lane], acc);
    float logit = (lane < NC) ? __fadd_rn(acc, bcs[lane]) : -__int_as_float(0x7f800000);
    float v = logit;
    int idx = lane;
    #pragma unroll
    for (int off = 16; off; off >>= 1) {
        float ov = __shfl_xor_sync(0xffffffffu, v, off);
        int oi = __shfl_xor_sync(0xffffffffu, idx, off);
        if (ov > v || (ov == v && oi < idx)) { v = ov; idx = oi; }
    }
    const float m = v;
    float e = (lane < NC) ? expf(logit - m) : 0.f;
    #pragma unroll
    for (int off = 16; off; off >>= 1) e += __shfl_xor_sync(0xffffffffu, e, off);
    const int ltar = g_ltar[b];
    const float lt = __shfl_sync(0xffffffffu, logit, ltar);
    if (lane == 0) {
        out[b] = (float)idx;
        g_loss[b] = (logf(e) + m) - lt;
    }
}

__global__ void __launch_bounds__(256) k_final(float* __restrict__ out) {
    __shared__ float red[256];
    const int tid = threadIdx.x;
    float s = 0.f;
    for (int i = tid; i < BATCH; i += 256) s += g_loss[i];
    red[tid] = s;
    __syncthreads();
    for (int st = 128; st; st >>= 1) {
        if (tid < st) red[tid] += red[tid + st];
        __syncthreads();
    }
    if (tid == 0) out[2 * BATCH] = red[0] / (float)BATCH;
}

extern "C" void kernel_launch(void* const* d_in, const int* in_sizes, int n_in,
                              void* d_out, int out_size) {
    const float* target  = (const float*)d_in[0];
    const int*   curlab  = (const int*)d_in[1];
    const float* hist    = (const float*)d_in[2];
    const int*   histlab = (const int*)d_in[3];
    const float* W1      = (const float*)d_in[4];
    const float* b1      = (const float*)d_in[5];
    const float* Wc      = (const float*)d_in[6];
    const float* bc      = (const float*)d_in[7];
    float* out = (float*)d_out;

    const int exsmem = (2 * CHUNK * STR + QROWS * STR + 8 * 4 * 64) * 4;
    cudaFuncSetAttribute(k_exact, cudaFuncAttributeMaxDynamicSharedMemorySize, exsmem);

    k_init<<<1, 32>>>(curlab);
    k_phist<<<NBANK / 256, 256>>>(curlab, histlab);
    k_pscan<<<1, 32>>>();
    k_pplace<<<NBANK / 256, 256>>>(curlab, histlab);
    dim3 g1(DB / BN, BATCH / BM);
    k_gemm1<<<g1, 256>>>(target, W1, b1);
    k_norm<<<NBANK / 256, 256>>>(hist);
    k_qnrm<<<(NBANK * 64) / 256, 256>>>(hist);
    dim3 gs(NC, 8);
    k_gsum<<<gs, 256>>>();
    k_gred<<<NC, 256>>>();
    k_screen<<<BATCH / 8, 256>>>();
    dim3 ge(NC, 64);
    k_exact<<<ge, 256, exsmem>>>();
    k_decide<<<BATCH / 8, 256>>>(out);
    k_logits<<<BATCH / 8, 256>>>(Wc, bc, out);
    k_final<<<1, 256>>>(out);
}